// round 12
// baseline (speedup 1.0000x reference)
#include <cuda_runtime.h>
#include <cuda_fp16.h>
#include <math.h>
#include <stdint.h>

// ---- problem dims ----
#define BB 2
#define SS 2048
#define INF 512
#define EE 1024
#define INNER 2048
#define UPW 4096          // 2*INNER
#define NHH 4
#define DHH 512
#define NTOK (BB*SS)      // 4096
#define BHN (BB*NHH)      // 8
#define EPS_CELL 1e-6f
#define LN_EPS 1e-5f
#define RSQRT_DH 0.044194173824159216f   // 1/sqrt(512)

// ---- fp32 scratch ----
__device__ float g_hin[NTOK*EE];
__device__ float g_up[NTOK*UPW];
__device__ float g_xconv[NTOK*INNER];
__device__ float g_q[NTOK*INNER];     // fp32 (gates path)
__device__ float g_k[NTOK*INNER];
__device__ float g_v[NTOK*INNER];
__device__ float g_ig[BHN*SS];
__device__ float g_fg[BHN*SS];
__device__ float g_gv[BHN*SS];
__device__ float g_av[BHN*SS];
__device__ float g_mv[BHN*SS];
__device__ float g_rowsum[BHN*SS];
__device__ float g_rnorm[BHN*SS];
__device__ float g_hatt[8388608];     // (B*NH, S, DH)
__device__ float g_pre[NTOK*EE];
// ---- fp16 GEMM operands, PACKED tile layout:
//   element (row, k) of an operand with K = tk*64 lives at
//   block = (row/128)*tk + k/64   (16 KB = 8192 halfs per block)
//   within block: (row%128)*64 + 8*((k/8 % 8) ^ (row%8)) + k%8
__device__ __half h_x16[NTOK*INF];
__device__ __half h_winT16[EE*INF];
__device__ __half h_xn16[NTOK*EE];
__device__ __half h_wupT16[UPW*EE];
__device__ __half h_q16[NTOK*INNER];     // per-bh packed (DH k-dim)
__device__ __half h_k16[NTOK*INNER];
__device__ __half h_sc16[33554432];      // per-bh packed (S k-dim)
__device__ __half h_vt16[8388608];       // per-bh packed (S k-dim)
__device__ __half h_hg16[NTOK*INNER];
__device__ __half h_wdnT16[EE*INNER];

// =====================================================================
// helpers
// =====================================================================
__device__ __forceinline__ size_t pidx(int row, int k, int tk) {
    return (((size_t)((row >> 7) * tk + (k >> 6))) << 13)
         + (size_t)(((row & 127) << 6)
         + ((((k >> 3) & 7) ^ (row & 7)) << 3) + (k & 7));
}
__device__ __forceinline__ uint32_t smem_u32(const void* p) {
    uint32_t a;
    asm("{ .reg .u64 t; cvta.to.shared.u64 t, %1; cvt.u32.u64 %0, t; }"
        : "=r"(a) : "l"(p));
    return a;
}
__device__ __forceinline__ void bulk_cp(uint32_t dst, const void* src,
                                        uint32_t bytes, uint32_t mbar) {
    asm volatile(
        "cp.async.bulk.shared::cluster.global.mbarrier::complete_tx::bytes "
        "[%0], [%1], %2, [%3];"
        :: "r"(dst), "l"(src), "r"(bytes), "r"(mbar) : "memory");
}
__device__ __forceinline__ void mbar_init(uint32_t mbar, uint32_t cnt) {
    asm volatile("mbarrier.init.shared.b64 [%0], %1;" :: "r"(mbar), "r"(cnt) : "memory");
}
__device__ __forceinline__ void mbar_expect_tx(uint32_t mbar, uint32_t bytes) {
    asm volatile("mbarrier.arrive.expect_tx.shared.b64 _, [%0], %1;"
                 :: "r"(mbar), "r"(bytes) : "memory");
}
__device__ __forceinline__ void mbar_wait(uint32_t mbar, uint32_t parity) {
    asm volatile(
        "{\n\t.reg .pred P;\n\t"
        "WL_%=:\n\t"
        "mbarrier.try_wait.parity.acquire.cta.shared::cta.b64 P, [%0], %1, 0x989680;\n\t"
        "@P bra.uni WD_%=;\n\t"
        "bra.uni WL_%=;\n\t"
        "WD_%=:\n\t}"
        :: "r"(mbar), "r"(parity) : "memory");
}
__device__ __forceinline__ void ldsm_x4(uint32_t* r, uint32_t addr) {
    asm volatile("ldmatrix.sync.aligned.m8n8.x4.shared.b16 {%0,%1,%2,%3}, [%4];"
                 : "=r"(r[0]), "=r"(r[1]), "=r"(r[2]), "=r"(r[3]) : "r"(addr));
}
__device__ __forceinline__ void mma_f16(float* c, const uint32_t* a,
                                        const uint32_t* b) {
    asm volatile(
        "mma.sync.aligned.m16n8k16.row.col.f32.f16.f16.f32 "
        "{%0,%1,%2,%3}, {%4,%5,%6,%7}, {%8,%9}, {%0,%1,%2,%3};"
        : "+f"(c[0]), "+f"(c[1]), "+f"(c[2]), "+f"(c[3])
        : "r"(a[0]), "r"(a[1]), "r"(a[2]), "r"(a[3]), "r"(b[0]), "r"(b[1]));
}

#define STG_BYTES 32768u                 // A 16KB + B 16KB per stage
#define SMEM_BYTES (3*32768 + 64)        // 3 stages + mbarriers
#define BHALF 16384u
#define NTHREADS 288                     // 8 compute warps + 1 producer warp

// =====================================================================
// FP16 mma.sync NT-GEMM on PACKED operands, 128x128 tile, K-chunk 64.
// R9-proven synchronization: compute warps __syncthreads AFTER the last
// LDSM of each chunk (BAR.SYNC drains the smem reads); the producer warp
// hits the same barrier and issues the refill AFTER it. mbarrier is used
// ONLY for bulk-copy completion (full barriers) — never for "empty".
// EPI 0: fp32 out (+bias, +optional resid)
// EPI 1: scores -> packed fp16 out (causal + exp(g[j]-a[i])), fused row-sums
// EPI 2: AV fp32 out (row scale by g_rnorm), causal nch = i0/64 + 2
// =====================================================================
template<int EPI>
__global__ void __launch_bounds__(NTHREADS, 2)
mma_gemm(const __half* __restrict__ A, const __half* __restrict__ B,
         float* __restrict__ Cf, __half* __restrict__ Ch,
         int ldc, int tka,
         const float* __restrict__ bias,
         const float* __restrict__ resid) {
    extern __shared__ __align__(1024) char smch[];
    const int tid = threadIdx.x;
    const int lane = tid & 31, wid = tid >> 5;
    const int warp_m = wid & 1, warp_n = wid >> 1;     // 2 x 4 (compute warps)
    const int qr = lane >> 2, qc = lane & 3;
    const int mt = blockIdx.y, nt = blockIdx.x;
    const int i0 = mt * 128, j0 = nt * 128;
    const int bh = blockIdx.z;

    if (EPI == 1) {
        if (j0 > i0) return;
        A += (size_t)bh << 20;
        B += (size_t)bh << 20;
        Ch += (size_t)bh << 22;
    }
    if (EPI == 2) {
        A += (size_t)bh << 22;
        B += (size_t)bh << 20;
        Cf += (size_t)bh * SS * DHH;
    }
    const int nch = (EPI == 2) ? ((i0 >> 6) + 2) : tka;

    const __half* Ablk = A + (size_t)(mt * tka) * 8192;
    const __half* Bblk = B + (size_t)(nt * tka) * 8192;

    const uint32_t smb = smem_u32(smch);
    const uint32_t fb0 = smb + 3 * STG_BYTES;        // full barriers (3 x 8B)

    if (tid == 0) {
        mbar_init(fb0, 1); mbar_init(fb0 + 8, 1); mbar_init(fb0 + 16, 1);
    }
    __syncthreads();

    // ---------------- producer warp (wid 8) ----------------
    if (wid == 8) {
        auto issue = [&](int t) {
            if (t < nch) {
                int s = t % 3;
                uint32_t fb = fb0 + s*8;
                uint32_t dst = smb + (uint32_t)s * STG_BYTES;
                mbar_expect_tx(fb, 32768u);
                bulk_cp(dst,         Ablk + (size_t)t * 8192, 16384u, fb);
                bulk_cp(dst + BHALF, Bblk + (size_t)t * 8192, 16384u, fb);
            }
        };
        if (lane == 0) { issue(0); issue(1); issue(2); }
        for (int t = 0; t < nch; ++t) {
            __syncthreads();              // pairs with compute warps' ks==3 bar
            if (lane == 0) issue(t + 3);  // refill AFTER the barrier (R9 rule)
        }
        return;
    }

    // ---------------- compute warps (wid 0..7) ----------------
    const int la = lane & 7, lg = lane >> 3;
    uint32_t adA[4], adB[2];
    #pragma unroll
    for (int ms = 0; ms < 4; ++ms) {
        int row = warp_m*64 + ms*16 + la + (lg & 1)*8;
        int c0 = lg >> 1;
        adA[ms] = smb + (uint32_t)(row*128 + 16*(c0 ^ (row & 7)));
    }
    #pragma unroll
    for (int nb = 0; nb < 2; ++nb) {
        int row = warp_n*32 + nb*16 + la + (lg >> 1)*8;
        int c0 = lg & 1;
        adB[nb] = smb + BHALF + (uint32_t)(row*128 + 16*(c0 ^ (row & 7)));
    }

    float acc[4][4][4];
    #pragma unroll
    for (int a = 0; a < 4; ++a)
        #pragma unroll
        for (int b = 0; b < 4; ++b)
            #pragma unroll
            for (int c = 0; c < 4; ++c) acc[a][b][c] = 0.f;

    for (int t = 0; t < nch; ++t) {
        const int s = t % 3;
        mbar_wait(fb0 + s*8, (uint32_t)((t / 3) & 1));

        const uint32_t stg = (uint32_t)s * STG_BYTES;
        #pragma unroll
        for (int ks = 0; ks < 4; ++ks) {
            const uint32_t kx = (uint32_t)(ks << 5);
            uint32_t a[4][4], b[2][4];
            #pragma unroll
            for (int ms = 0; ms < 4; ++ms)
                ldsm_x4(a[ms], (adA[ms] + stg) ^ kx);
            #pragma unroll
            for (int nb = 0; nb < 2; ++nb)
                ldsm_x4(b[nb], (adB[nb] + stg) ^ kx);
            if (ks == 3) {
                // all LDSMs of this stage issued; BAR.SYNC drains them,
                // then the producer refills the stage (after its bar).
                __syncthreads();
            }
            #pragma unroll
            for (int ms = 0; ms < 4; ++ms)
                #pragma unroll
                for (int nn = 0; nn < 4; ++nn)
                    mma_f16(acc[ms][nn], a[ms], &b[nn >> 1][(nn & 1) * 2]);
        }
    }

    // epilogue (compute warps only)
    #pragma unroll
    for (int ms = 0; ms < 4; ++ms) {
        const int r0 = i0 + warp_m*64 + ms*16 + qr;
        float rs0 = 0.f, rs1 = 0.f;
        #pragma unroll
        for (int ns = 0; ns < 4; ++ns) {
            const int c0 = j0 + warp_n*32 + ns*8 + qc*2;
            float v00 = acc[ms][ns][0], v01 = acc[ms][ns][1];
            float v10 = acc[ms][ns][2], v11 = acc[ms][ns][3];
            if (EPI == 0) {
                float b0 = bias[c0], b1 = bias[c0+1];
                v00 += b0; v01 += b1; v10 += b0; v11 += b1;
                if (resid) {
                    v00 += resid[(size_t)r0*ldc + c0];
                    v01 += resid[(size_t)r0*ldc + c0 + 1];
                    v10 += resid[(size_t)(r0+8)*ldc + c0];
                    v11 += resid[(size_t)(r0+8)*ldc + c0 + 1];
                }
                *(float2*)(Cf + (size_t)r0*ldc + c0)     = make_float2(v00, v01);
                *(float2*)(Cf + (size_t)(r0+8)*ldc + c0) = make_float2(v10, v11);
            } else if (EPI == 1) {
                float ga = g_gv[bh*SS + c0], gb = g_gv[bh*SS + c0 + 1];
                float a0 = g_av[bh*SS + r0], a1 = g_av[bh*SS + r0 + 8];
                v00 = (c0   <= r0  ) ? v00*RSQRT_DH*__expf(ga-a0) : 0.f;
                v01 = (c0+1 <= r0  ) ? v01*RSQRT_DH*__expf(gb-a0) : 0.f;
                v10 = (c0   <= r0+8) ? v10*RSQRT_DH*__expf(ga-a1) : 0.f;
                v11 = (c0+1 <= r0+8) ? v11*RSQRT_DH*__expf(gb-a1) : 0.f;
                rs0 += v00 + v01; rs1 += v10 + v11;
                *(__half2*)(Ch + pidx(r0,   c0, 32)) = __floats2half2_rn(v00, v01);
                *(__half2*)(Ch + pidx(r0+8, c0, 32)) = __floats2half2_rn(v10, v11);
            } else {
                float rn0 = g_rnorm[bh*SS + r0], rn1 = g_rnorm[bh*SS + r0 + 8];
                v00 *= rn0; v01 *= rn0; v10 *= rn1; v11 *= rn1;
                *(float2*)(Cf + (size_t)r0*ldc + c0)     = make_float2(v00, v01);
                *(float2*)(Cf + (size_t)(r0+8)*ldc + c0) = make_float2(v10, v11);
            }
        }
        if (EPI == 1) {
            rs0 += __shfl_xor_sync(0xFFFFFFFF, rs0, 1);
            rs0 += __shfl_xor_sync(0xFFFFFFFF, rs0, 2);
            rs1 += __shfl_xor_sync(0xFFFFFFFF, rs1, 1);
            rs1 += __shfl_xor_sync(0xFFFFFFFF, rs1, 2);
            if (qc == 0) {
                atomicAdd(g_rowsum + bh*SS + r0, rs0);
                atomicAdd(g_rowsum + bh*SS + r0 + 8, rs1);
            }
        }
    }
}

// =====================================================================
// Tiled transpose to PACKED fp16: element (n=c, k=r)
// =====================================================================
__global__ void __launch_bounds__(256)
transpose_k(const float* __restrict__ in, __half* __restrict__ out,
            int R, int Ccols) {
    __shared__ float t[32][33];
    int r0 = blockIdx.y*32, c0 = blockIdx.x*32;
    int tx = threadIdx.x & 31, ty = threadIdx.x >> 5;
    int tk = R >> 6;
    #pragma unroll
    for (int i = ty; i < 32; i += 8)
        t[i][tx] = in[(size_t)(r0+i)*Ccols + c0 + tx];
    __syncthreads();
    #pragma unroll
    for (int i = ty; i < 32; i += 8)
        out[pidx(c0+i, r0+tx, tk)] = __float2half_rn(t[tx][i]);
}

// h_vt16 packed: per bh, element (row=d, k=s)
__global__ void __launch_bounds__(256)
vt_kernel() {
    __shared__ float t[32][33];
    int bh = blockIdx.z, b = bh >> 2, nh = bh & 3;
    int s0 = blockIdx.y*32, d0 = blockIdx.x*32;
    int tx = threadIdx.x & 31, ty = threadIdx.x >> 5;
    __half* dst = h_vt16 + ((size_t)bh << 20);
    #pragma unroll
    for (int i = ty; i < 32; i += 8)
        t[i][tx] = g_v[(size_t)(b*SS + s0 + i)*INNER + nh*DHH + d0 + tx];
    __syncthreads();
    #pragma unroll
    for (int i = ty; i < 32; i += 8)
        dst[pidx(d0+i, s0+tx, 32)] = __float2half_rn(t[tx][i]);
}

// x -> packed fp16 (row=tok, k 0..511)
__global__ void __launch_bounds__(256)
cvt_kernel(const float* __restrict__ in, __half* __restrict__ out) {
    int i = blockIdx.x*256 + threadIdx.x;
    out[pidx(i >> 9, i & 511, 8)] = __float2half_rn(in[i]);
}

// =====================================================================
// LayerNorm; HALF=1 writes packed __half, HALF=0 writes fp32 rows
// (float4 reduction pass)
// =====================================================================
template<int HALF>
__global__ void __launch_bounds__(256)
ln_kernel(const float* __restrict__ in, const float* __restrict__ w,
          float* __restrict__ outf, __half* __restrict__ outh, int cols) {
    int row = blockIdx.x, tid = threadIdx.x;
    const float* xr = in + (size_t)row * cols;
    const float4* xr4 = (const float4*)xr;
    int n4 = cols >> 2;
    float s = 0.f, s2 = 0.f;
    for (int c = tid; c < n4; c += 256) {
        float4 v = xr4[c];
        s  += (v.x + v.y) + (v.z + v.w);
        s2 += (v.x*v.x + v.y*v.y) + (v.z*v.z + v.w*v.w);
    }
    __shared__ float shs[256], shq[256];
    shs[tid] = s; shq[tid] = s2; __syncthreads();
    for (int off = 128; off > 0; off >>= 1) {
        if (tid < off) { shs[tid] += shs[tid+off]; shq[tid] += shq[tid+off]; }
        __syncthreads();
    }
    float mean = shs[0] / cols;
    float var = shq[0] / cols - mean * mean;
    float inv = rsqrtf(var + LN_EPS);
    int tk = cols >> 6;
    for (int c = tid; c < cols; c += 256) {
        float v = (xr[c] - mean) * inv * w[c];
        if (HALF) outh[pidx(row, c, tk)] = __float2half_rn(v);
        else      outf[(size_t)row * cols + c] = v;
    }
}

// =====================================================================
// Causal depthwise conv1d (K=4) + SiLU — rolling window, 8 s per thread
// =====================================================================
__global__ void __launch_bounds__(256)
conv_kernel(const float* __restrict__ conv_w, const float* __restrict__ conv_b) {
    int c  = blockIdx.x * 256 + threadIdx.x;
    int s0 = blockIdx.y * 8;
    int b  = blockIdx.z;
    const float* base = g_up + (size_t)(b*SS) * UPW + c;
    float* obase = g_xconv + (size_t)(b*SS) * INNER + c;
    float w0 = conv_w[c*4+0], w1 = conv_w[c*4+1];
    float w2 = conv_w[c*4+2], w3 = conv_w[c*4+3];
    float cb = conv_b[c];
    float x0 = (s0 >= 3) ? base[(size_t)(s0-3)*UPW] : 0.f;
    float x1 = (s0 >= 2) ? base[(size_t)(s0-2)*UPW] : 0.f;
    float x2 = (s0 >= 1) ? base[(size_t)(s0-1)*UPW] : 0.f;
    #pragma unroll
    for (int i = 0; i < 8; ++i) {
        int s = s0 + i;
        float x3 = base[(size_t)s*UPW];
        float acc = cb + x0*w0 + x1*w1 + x2*w2 + x3*w3;
        float sig = 1.f / (1.f + expf(-acc));
        obase[(size_t)s*INNER] = acc * sig;
        x0 = x1; x1 = x2; x2 = x3;
    }
}

// =====================================================================
// Headwise q/k/v: fp32 (gates) + packed fp16 q/k (score GEMM, per bh)
// =====================================================================
__global__ void __launch_bounds__(256)
headwise_kernel(const float* __restrict__ q_w, const float* __restrict__ q_b,
                const float* __restrict__ k_w, const float* __restrict__ k_b,
                const float* __restrict__ v_w, const float* __restrict__ v_b) {
    int idx = blockIdx.x * 256 + threadIdx.x;
    int h = idx & 511;
    int tok = idx >> 9;
    const float* xc = g_xconv + (size_t)tok * INNER + h*4;
    const float* xm = g_up    + (size_t)tok * UPW   + h*4;
    float c0=xc[0], c1=xc[1], c2=xc[2], c3=xc[3];
    float m0=xm[0], m1=xm[1], m2=xm[2], m3=xm[3];
    int wb = h * 16;
    int b = tok >> 11, s = tok & (SS-1);
    #pragma unroll
    for (int o = 0; o < 4; ++o) {
        const float* wq = q_w + wb + o*4;
        const float* wk = k_w + wb + o*4;
        const float* wv = v_w + wb + o*4;
        int oc = h*4 + o;
        float qv = q_b[oc] + wq[0]*c0 + wq[1]*c1 + wq[2]*c2 + wq[3]*c3;
        float kv = k_b[oc] + wk[0]*c0 + wk[1]*c1 + wk[2]*c2 + wk[3]*c3;
        float vv = v_b[oc] + wv[0]*m0 + wv[1]*m1 + wv[2]*m2 + wv[3]*m3;
        g_q[(size_t)tok*INNER + oc] = qv;
        g_k[(size_t)tok*INNER + oc] = kv;
        g_v[(size_t)tok*INNER + oc] = vv;
        int nh = oc >> 9, d = oc & 511;
        size_t pbase = ((size_t)(b*NHH + nh) << 20) + pidx(s, d, 8);
        h_q16[pbase] = __float2half_rn(qv);
        h_k16[pbase] = __float2half_rn(kv);
    }
}

// =====================================================================
// Gate pre-activations (fp32 path, float4 loads)
// =====================================================================
__global__ void __launch_bounds__(256)
gates_kernel(const float* __restrict__ ig_w, const float* __restrict__ ig_b,
             const float* __restrict__ fg_w, const float* __restrict__ fg_b) {
    int tok = blockIdx.x, tid = threadIdx.x;
    float aig[4] = {0,0,0,0}, afg[4] = {0,0,0,0};
    for (int f = tid*4; f < 3*INNER; f += 1024) {
        float4 xv;
        if (f < INNER)            xv = *(const float4*)(g_q + (size_t)tok*INNER + f);
        else if (f < 2*INNER)     xv = *(const float4*)(g_k + (size_t)tok*INNER + f - INNER);
        else                      xv = *(const float4*)(g_v + (size_t)tok*INNER + f - 2*INNER);
        #pragma unroll
        for (int j = 0; j < 4; ++j) {
            float xs = (j == 0) ? xv.x : (j == 1) ? xv.y : (j == 2) ? xv.z : xv.w;
            float4 wi = *(const float4*)(ig_w + (size_t)(f + j) * 4);
            float4 wf = *(const float4*)(fg_w + (size_t)(f + j) * 4);
            aig[0] += xs*wi.x; aig[1] += xs*wi.y; aig[2] += xs*wi.z; aig[3] += xs*wi.w;
            afg[0] += xs*wf.x; afg[1] += xs*wf.y; afg[2] += xs*wf.z; afg[3] += xs*wf.w;
        }
    }
    __shared__ float sh[8*256];
    #pragma unroll
    for (int n = 0; n < 4; ++n) { sh[n*256+tid] = aig[n]; sh[(4+n)*256+tid] = afg[n]; }
    __syncthreads();
    for (int off = 128; off > 0; off >>= 1) {
        if (tid < off)
            #pragma unroll
            for (int m = 0; m < 8; ++m) sh[m*256+tid] += sh[m*256+tid+off];
        __syncthreads();
    }
    if (tid == 0) {
        int b = tok >> 11, s = tok & (SS-1);
        #pragma unroll
        for (int n = 0; n < 4; ++n) {
            g_ig[(b*NHH+n)*SS + s] = sh[n*256] + ig_b[n];
            g_fg[(b*NHH+n)*SS + s] = sh[(4+n)*256] + fg_b[n];
        }
    }
}

// =====================================================================
// Per-(b,nh) scans: cum, g, a, m.  Also zeroes g_rowsum.
// =====================================================================
__global__ void __launch_bounds__(256)
scan_kernel() {
    int bh = blockIdx.x, tid = threadIdx.x;
    const int PERT = SS / 256;
    __shared__ float sh[256];
    int base = bh*SS + tid*PERT;
    float lf[PERT]; float lsum = 0.f;
    #pragma unroll
    for (int r = 0; r < PERT; ++r) {
        float f = g_fg[base + r];
        float l = (f >= 0.f) ? -log1pf(expf(-f)) : (f - log1pf(expf(f)));
        lf[r] = l; lsum += l;
    }
    sh[tid] = lsum; __syncthreads();
    for (int off = 1; off < 256; off <<= 1) {
        float v = sh[tid];
        float p = (tid >= off) ? sh[tid-off] : 0.f;
        __syncthreads();
        sh[tid] = v + p;
        __syncthreads();
    }
    float cumoff = sh[tid] - lsum;
    __syncthreads();
    float run = cumoff, lmax = -INFINITY;
    float cumv[PERT], gloc[PERT], gmax[PERT];
    #pragma unroll
    for (int r = 0; r < PERT; ++r) {
        run += lf[r];
        cumv[r] = run;
        float gg = g_ig[base + r] - run;
        gloc[r] = gg;
        lmax = fmaxf(lmax, gg);
        gmax[r] = lmax;
    }
    sh[tid] = lmax; __syncthreads();
    for (int off = 1; off < 256; off <<= 1) {
        float v = sh[tid];
        float p = (tid >= off) ? sh[tid-off] : -INFINITY;
        __syncthreads();
        sh[tid] = fmaxf(v, p);
        __syncthreads();
    }
    float exmax = (tid == 0) ? -INFINITY : sh[tid-1];
    #pragma unroll
    for (int r = 0; r < PERT; ++r) {
        float a = fmaxf(exmax, gmax[r]);
        g_gv[base + r] = gloc[r];
        g_av[base + r] = a;
        g_mv[base + r] = cumv[r] + a;
        g_rowsum[base + r] = 0.f;
    }
}

// =====================================================================
// Finalize row norm from fused atomics
// =====================================================================
__global__ void __launch_bounds__(256)
rnorm_fin_kernel() {
    int idx = blockIdx.x*256 + threadIdx.x;
    float norm = fmaxf(fabsf(g_rowsum[idx]), expf(-g_mv[idx]));
    g_rnorm[idx] = 1.f / (norm + EPS_CELL);
}

// =====================================================================
// Head group-norm + skip + output gate -> packed fp16 (down GEMM)
// (float4 reduction pass)
// =====================================================================
__global__ void __launch_bounds__(256)
hgate_kernel(const float* __restrict__ onorm_w, const float* __restrict__ skip) {
    int idx = blockIdx.x;
    int s = idx & (SS-1);
    int bhn = idx >> 11;
    int nh = bhn & 3, b = bhn >> 2;
    int tid = threadIdx.x;
    const float* hrow = g_hatt + (size_t)idx * DHH;
    const float4* h4 = (const float4*)hrow;
    float sm = 0.f, sq = 0.f;
    for (int d = tid; d < DHH/4; d += 256) {
        float4 v = h4[d];
        sm += (v.x + v.y) + (v.z + v.w);
        sq += (v.x*v.x + v.y*v.y) + (v.z*v.z + v.w*v.w);
    }
    __shared__ float shs[256], shq[256];
    shs[tid] = sm; shq[tid] = sq; __syncthreads();
    for (int off = 128; off > 0; off >>= 1) {
        if (tid < off) { shs[tid] += shs[tid+off]; shq[tid] += shq[tid+off]; }
        __syncthreads();
    }
    float mean = shs[0] / DHH;
    float var = shq[0] / DHH - mean * mean;
    float inv = rsqrtf(var + LN_EPS);
    size_t tq = (size_t)(b*SS + s);
    for (int d = tid; d < DHH; d += 256) {
        int c = nh*DHH + d;
        float hn = (hrow[d] - mean) * inv * onorm_w[c];
        float xc = g_xconv[tq*INNER + c];
        float zz = g_up[tq*UPW + INNER + c];
        float silz = zz / (1.f + expf(-zz));
        h_hg16[pidx((int)tq, c, 32)] = __float2half_rn((hn + skip[c]*xc) * silz);
    }
}

// =====================================================================
extern "C" void kernel_launch(void* const* d_in, const int* in_sizes, int n_in,
                              void* d_out, int out_size) {
    const float* x      = (const float*)d_in[0];
    const float* w_in   = (const float*)d_in[1];
    const float* b_in   = (const float*)d_in[2];
    const float* ln1_w  = (const float*)d_in[3];
    const float* w_up   = (const float*)d_in[4];
    const float* b_up   = (const float*)d_in[5];
    const float* conv_w = (const float*)d_in[6];
    const float* conv_b = (const float*)d_in[7];
    const float* q_w    = (const float*)d_in[8];
    const float* q_b    = (const float*)d_in[9];
    const float* k_w    = (const float*)d_in[10];
    const float* k_b    = (const float*)d_in[11];
    const float* v_w    = (const float*)d_in[12];
    const float* v_b    = (const float*)d_in[13];
    const float* ig_w   = (const float*)d_in[14];
    const float* ig_b   = (const float*)d_in[15];
    const float* fg_w   = (const float*)d_in[16];
    const float* fg_b   = (const float*)d_in[17];
    const float* onorm_w= (const float*)d_in[18];
    const float* skip   = (const float*)d_in[19];
    const float* w_down = (const float*)d_in[20];
    const float* b_down = (const float*)d_in[21];
    const float* post_w = (const float*)d_in[22];
    float* out = (float*)d_out;

    float *p_hin, *p_pre, *p_hatt, *p_up;
    __half *p_x16, *p_winT, *p_wupT, *p_wdnT, *p_xn16, *p_q16, *p_k16;
    __half *p_sc16, *p_vt16, *p_hg16;
    cudaGetSymbolAddress((void**)&p_hin, g_hin);
    cudaGetSymbolAddress((void**)&p_pre, g_pre);
    cudaGetSymbolAddress((void**)&p_hatt, g_hatt);
    cudaGetSymbolAddress((void**)&p_up, g_up);
    cudaGetSymbolAddress((void**)&p_x16, h_x16);
    cudaGetSymbolAddress((void**)&p_winT, h_winT16);
    cudaGetSymbolAddress((void**)&p_wupT, h_wupT16);
    cudaGetSymbolAddress((void**)&p_wdnT, h_wdnT16);
    cudaGetSymbolAddress((void**)&p_xn16, h_xn16);
    cudaGetSymbolAddress((void**)&p_q16, h_q16);
    cudaGetSymbolAddress((void**)&p_k16, h_k16);
    cudaGetSymbolAddress((void**)&p_sc16, h_sc16);
    cudaGetSymbolAddress((void**)&p_vt16, h_vt16);
    cudaGetSymbolAddress((void**)&p_hg16, h_hg16);

    static int attr_done = 0;
    if (!attr_done) {
        cudaFuncSetAttribute(mma_gemm<0>, cudaFuncAttributeMaxDynamicSharedMemorySize, SMEM_BYTES);
        cudaFuncSetAttribute(mma_gemm<1>, cudaFuncAttributeMaxDynamicSharedMemorySize, SMEM_BYTES);
        cudaFuncSetAttribute(mma_gemm<2>, cudaFuncAttributeMaxDynamicSharedMemorySize, SMEM_BYTES);
        attr_done = 1;
    }

    // weight transposes + fp16 conversion (packed layouts)
    transpose_k<<<dim3(EE/32, INF/32), 256>>>(w_in, p_winT, INF, EE);
    transpose_k<<<dim3(UPW/32, EE/32), 256>>>(w_up, p_wupT, EE, UPW);
    transpose_k<<<dim3(EE/32, INNER/32), 256>>>(w_down, p_wdnT, INNER, EE);
    cvt_kernel<<<(NTOK*INF)/256, 256>>>(x, p_x16);

    // 1. h_in = x @ w_in + b_in      (tka = 512/64 = 8)
    mma_gemm<0><<<dim3(EE/128, NTOK/128, 1), NTHREADS, SMEM_BYTES>>>(p_x16, p_winT, p_hin, nullptr, EE, 8, b_in, nullptr);
    // 2. xn = LN(h_in)  (packed fp16)
    ln_kernel<1><<<NTOK, 256>>>(p_hin, ln1_w, nullptr, p_xn16, EE);
    // 3. up = xn @ w_up + b_up       (tka = 1024/64 = 16)
    mma_gemm<0><<<dim3(UPW/128, NTOK/128, 1), NTHREADS, SMEM_BYTES>>>(p_xn16, p_wupT, p_up, nullptr, UPW, 16, b_up, nullptr);
    // 4. conv + SiLU
    conv_kernel<<<dim3(INNER/256, SS/8, BB), 256>>>(conv_w, conv_b);
    // 5. headwise q/k/v
    headwise_kernel<<<(NTOK*512)/256, 256>>>(q_w, q_b, k_w, k_b, v_w, v_b);
    // 6-7. gates + scans (scan zeroes g_rowsum)
    gates_kernel<<<NTOK, 256>>>(ig_w, ig_b, fg_w, fg_b);
    scan_kernel<<<BHN, 256>>>();
    // transpose V per head (packed)
    vt_kernel<<<dim3(DHH/32, SS/32, BHN), 256>>>();
    // 8. scores (causal, exp epilogue, packed fp16 out, fused row-sums; tka=8)
    mma_gemm<1><<<dim3(SS/128, SS/128, BHN), NTHREADS, SMEM_BYTES>>>(p_q16, p_k16, nullptr, p_sc16, SS, 8, nullptr, nullptr);
    // 9. finalize row norm
    rnorm_fin_kernel<<<(BHN*SS)/256, 256>>>();
    // 10. h = (C * rnorm) @ V        (tka = 32, causal nch)
    mma_gemm<2><<<dim3(DHH/128, SS/128, BHN), NTHREADS, SMEM_BYTES>>>(p_sc16, p_vt16, p_hatt, nullptr, DHH, 32, nullptr, nullptr);
    // 11. head norm + skip + gate (packed fp16)
    hgate_kernel<<<BHN*SS, 256>>>(onorm_w, skip);
    // 12. y = h_gated @ w_down + b_down + h_in   (tka = 32)
    mma_gemm<0><<<dim3(EE/128, NTOK/128, 1), NTHREADS, SMEM_BYTES>>>(p_hg16, p_wdnT, p_pre, nullptr, EE, 32, b_down, p_hin);
    // 13. out = LN(pre)  (fp32 final output)
    ln_kernel<0><<<NTOK, 256>>>(p_pre, post_w, out, nullptr, EE);
}

// round 13
// speedup vs baseline: 1.0221x; 1.0221x over previous
#include <cuda_runtime.h>
#include <cuda_fp16.h>
#include <math.h>
#include <stdint.h>

// ---- problem dims ----
#define BB 2
#define SS 2048
#define INF 512
#define EE 1024
#define INNER 2048
#define UPW 4096          // 2*INNER
#define NHH 4
#define DHH 512
#define NTOK (BB*SS)      // 4096
#define BHN (BB*NHH)      // 8
#define EPS_CELL 1e-6f
#define LN_EPS 1e-5f
#define RSQRT_DH 0.044194173824159216f   // 1/sqrt(512)

// ---- fp32 scratch ----
__device__ float g_hin[NTOK*EE];
__device__ float g_up[NTOK*UPW];
__device__ float g_xconv[NTOK*INNER];
__device__ float g_q[NTOK*INNER];     // fp32 (gates path)
__device__ float g_k[NTOK*INNER];
__device__ float g_v[NTOK*INNER];
__device__ float g_ig[BHN*SS];
__device__ float g_fg[BHN*SS];
__device__ float g_gv[BHN*SS];
__device__ float g_av[BHN*SS];
__device__ float g_mv[BHN*SS];
__device__ float g_rowsum[BHN*SS];
__device__ float g_hatt[8388608];     // (B*NH, S, DH)
__device__ float g_pre[NTOK*EE];
// ---- fp16 GEMM operands, PACKED tile layout:
//   element (row, k) of an operand with K = tk*64 lives at
//   block = (row/128)*tk + k/64   (16 KB = 8192 halfs per block)
//   within block: (row%128)*64 + 8*((k/8 % 8) ^ (row%8)) + k%8
__device__ __half h_x16[NTOK*INF];
__device__ __half h_winT16[EE*INF];
__device__ __half h_xn16[NTOK*EE];
__device__ __half h_wupT16[UPW*EE];
__device__ __half h_q16[NTOK*INNER];     // per-bh packed (DH k-dim)
__device__ __half h_k16[NTOK*INNER];
__device__ __half h_sc16[33554432];      // per-bh packed (S k-dim)
__device__ __half h_vt16[8388608];       // per-bh packed (S k-dim)
__device__ __half h_hg16[NTOK*INNER];
__device__ __half h_wdnT16[EE*INNER];

// =====================================================================
// helpers
// =====================================================================
__device__ __forceinline__ size_t pidx(int row, int k, int tk) {
    return (((size_t)((row >> 7) * tk + (k >> 6))) << 13)
         + (size_t)(((row & 127) << 6)
         + ((((k >> 3) & 7) ^ (row & 7)) << 3) + (k & 7));
}
__device__ __forceinline__ uint32_t smem_u32(const void* p) {
    uint32_t a;
    asm("{ .reg .u64 t; cvta.to.shared.u64 t, %1; cvt.u32.u64 %0, t; }"
        : "=r"(a) : "l"(p));
    return a;
}
__device__ __forceinline__ void bulk_cp(uint32_t dst, const void* src,
                                        uint32_t bytes, uint32_t mbar) {
    asm volatile(
        "cp.async.bulk.shared::cluster.global.mbarrier::complete_tx::bytes "
        "[%0], [%1], %2, [%3];"
        :: "r"(dst), "l"(src), "r"(bytes), "r"(mbar) : "memory");
}
__device__ __forceinline__ void mbar_init(uint32_t mbar, uint32_t cnt) {
    asm volatile("mbarrier.init.shared.b64 [%0], %1;" :: "r"(mbar), "r"(cnt) : "memory");
}
__device__ __forceinline__ void mbar_expect_tx(uint32_t mbar, uint32_t bytes) {
    asm volatile("mbarrier.arrive.expect_tx.shared.b64 _, [%0], %1;"
                 :: "r"(mbar), "r"(bytes) : "memory");
}
__device__ __forceinline__ void mbar_wait(uint32_t mbar, uint32_t parity) {
    asm volatile(
        "{\n\t.reg .pred P;\n\t"
        "WL_%=:\n\t"
        "mbarrier.try_wait.parity.acquire.cta.shared::cta.b64 P, [%0], %1, 0x989680;\n\t"
        "@P bra.uni WD_%=;\n\t"
        "bra.uni WL_%=;\n\t"
        "WD_%=:\n\t}"
        :: "r"(mbar), "r"(parity) : "memory");
}
__device__ __forceinline__ void ldsm_x4(uint32_t* r, uint32_t addr) {
    asm volatile("ldmatrix.sync.aligned.m8n8.x4.shared.b16 {%0,%1,%2,%3}, [%4];"
                 : "=r"(r[0]), "=r"(r[1]), "=r"(r[2]), "=r"(r[3]) : "r"(addr));
}
__device__ __forceinline__ void mma_f16(float* c, const uint32_t* a,
                                        const uint32_t* b) {
    asm volatile(
        "mma.sync.aligned.m16n8k16.row.col.f32.f16.f16.f32 "
        "{%0,%1,%2,%3}, {%4,%5,%6,%7}, {%8,%9}, {%0,%1,%2,%3};"
        : "+f"(c[0]), "+f"(c[1]), "+f"(c[2]), "+f"(c[3])
        : "r"(a[0]), "r"(a[1]), "r"(a[2]), "r"(a[3]), "r"(b[0]), "r"(b[1]));
}

#define STG_BYTES 32768u                 // A 16KB + B 16KB per stage
#define SMEM_BYTES (3*32768 + 64)        // 3 stages + mbarriers
#define BHALF 16384u

// =====================================================================
// FP16 mma.sync NT-GEMM on PACKED operands, 128x128 tile, K-chunk 64.
// R9 configuration (proven fastest + correct): 256 threads, 3-stage
// bulk-copy ring; per chunk the compute path does LDSMs, then a
// __syncthreads (drains smem reads), then tid-0 issues the refill,
// then the final MMA batch.
// EPI 0: fp32 out (+bias, +optional resid)
// EPI 1: scores -> packed fp16 out (causal + exp(g[j]-a[i])), fused row-sums
// EPI 2: AV fp32 out (row scale computed inline from rowsum/mv)
// =====================================================================
template<int EPI>
__global__ void __launch_bounds__(256, 2)
mma_gemm(const __half* __restrict__ A, const __half* __restrict__ B,
         float* __restrict__ Cf, __half* __restrict__ Ch,
         int ldc, int tka,
         const float* __restrict__ bias,
         const float* __restrict__ resid) {
    extern __shared__ __align__(1024) char smch[];
    const int tid = threadIdx.x;
    const int lane = tid & 31, wid = tid >> 5;
    const int warp_m = wid & 1, warp_n = wid >> 1;     // 2 x 4
    const int qr = lane >> 2, qc = lane & 3;
    const int mt = blockIdx.y, nt = blockIdx.x;
    const int i0 = mt * 128, j0 = nt * 128;
    const int bh = blockIdx.z;

    if (EPI == 1) {
        if (j0 > i0) return;
        A += (size_t)bh << 20;
        B += (size_t)bh << 20;
        Ch += (size_t)bh << 22;
    }
    if (EPI == 2) {
        A += (size_t)bh << 22;
        B += (size_t)bh << 20;
        Cf += (size_t)bh * SS * DHH;
    }
    const int nch = (EPI == 2) ? ((i0 >> 6) + 2) : tka;

    const __half* Ablk = A + (size_t)(mt * tka) * 8192;
    const __half* Bblk = B + (size_t)(nt * tka) * 8192;

    const uint32_t smb = smem_u32(smch);
    const uint32_t fb0 = smb + 3 * STG_BYTES;

    if (tid == 0) {
        mbar_init(fb0, 1); mbar_init(fb0 + 8, 1); mbar_init(fb0 + 16, 1);
    }
    __syncthreads();

    const int la = lane & 7, lg = lane >> 3;
    uint32_t adA[4], adB[2];
    #pragma unroll
    for (int ms = 0; ms < 4; ++ms) {
        int row = warp_m*64 + ms*16 + la + (lg & 1)*8;
        int c0 = lg >> 1;
        adA[ms] = smb + (uint32_t)(row*128 + 16*(c0 ^ (row & 7)));
    }
    #pragma unroll
    for (int nb = 0; nb < 2; ++nb) {
        int row = warp_n*32 + nb*16 + la + (lg >> 1)*8;
        int c0 = lg & 1;
        adB[nb] = smb + BHALF + (uint32_t)(row*128 + 16*(c0 ^ (row & 7)));
    }

    float acc[4][4][4];
    #pragma unroll
    for (int a = 0; a < 4; ++a)
        #pragma unroll
        for (int b = 0; b < 4; ++b)
            #pragma unroll
            for (int c = 0; c < 4; ++c) acc[a][b][c] = 0.f;

    auto issue = [&](int t) {
        if (t < nch && tid == 0) {
            int s = t % 3;
            uint32_t fb = fb0 + s*8;
            uint32_t dst = smb + (uint32_t)s * STG_BYTES;
            mbar_expect_tx(fb, 32768u);
            bulk_cp(dst,         Ablk + (size_t)t * 8192, 16384u, fb);
            bulk_cp(dst + BHALF, Bblk + (size_t)t * 8192, 16384u, fb);
        }
    };
    issue(0); issue(1); issue(2);

    for (int t = 0; t < nch; ++t) {
        const int s = t % 3;
        mbar_wait(fb0 + s*8, (uint32_t)((t / 3) & 1));

        const uint32_t stg = (uint32_t)s * STG_BYTES;
        #pragma unroll
        for (int ks = 0; ks < 4; ++ks) {
            const uint32_t kx = (uint32_t)(ks << 5);
            uint32_t a[4][4], b[2][4];
            #pragma unroll
            for (int ms = 0; ms < 4; ++ms)
                ldsm_x4(a[ms], (adA[ms] + stg) ^ kx);
            #pragma unroll
            for (int nb = 0; nb < 2; ++nb)
                ldsm_x4(b[nb], (adB[nb] + stg) ^ kx);
            if (ks == 3) {
                // all LDSMs of this stage issued; BAR.SYNC drains them,
                // then the refill is issued (R9-proven ordering).
                __syncthreads();
                issue(t + 3);
            }
            #pragma unroll
            for (int ms = 0; ms < 4; ++ms)
                #pragma unroll
                for (int nn = 0; nn < 4; ++nn)
                    mma_f16(acc[ms][nn], a[ms], &b[nn >> 1][(nn & 1) * 2]);
        }
    }

    // epilogue
    #pragma unroll
    for (int ms = 0; ms < 4; ++ms) {
        const int r0 = i0 + warp_m*64 + ms*16 + qr;
        float rs0 = 0.f, rs1 = 0.f;
        float rn0 = 0.f, rn1 = 0.f;
        if (EPI == 2) {
            float s0 = g_rowsum[bh*SS + r0], s1 = g_rowsum[bh*SS + r0 + 8];
            rn0 = 1.f / (fmaxf(fabsf(s0), expf(-g_mv[bh*SS + r0])) + EPS_CELL);
            rn1 = 1.f / (fmaxf(fabsf(s1), expf(-g_mv[bh*SS + r0 + 8])) + EPS_CELL);
        }
        #pragma unroll
        for (int ns = 0; ns < 4; ++ns) {
            const int c0 = j0 + warp_n*32 + ns*8 + qc*2;
            float v00 = acc[ms][ns][0], v01 = acc[ms][ns][1];
            float v10 = acc[ms][ns][2], v11 = acc[ms][ns][3];
            if (EPI == 0) {
                float b0 = bias[c0], b1 = bias[c0+1];
                v00 += b0; v01 += b1; v10 += b0; v11 += b1;
                if (resid) {
                    v00 += resid[(size_t)r0*ldc + c0];
                    v01 += resid[(size_t)r0*ldc + c0 + 1];
                    v10 += resid[(size_t)(r0+8)*ldc + c0];
                    v11 += resid[(size_t)(r0+8)*ldc + c0 + 1];
                }
                *(float2*)(Cf + (size_t)r0*ldc + c0)     = make_float2(v00, v01);
                *(float2*)(Cf + (size_t)(r0+8)*ldc + c0) = make_float2(v10, v11);
            } else if (EPI == 1) {
                float ga = g_gv[bh*SS + c0], gb = g_gv[bh*SS + c0 + 1];
                float a0 = g_av[bh*SS + r0], a1 = g_av[bh*SS + r0 + 8];
                v00 = (c0   <= r0  ) ? v00*RSQRT_DH*__expf(ga-a0) : 0.f;
                v01 = (c0+1 <= r0  ) ? v01*RSQRT_DH*__expf(gb-a0) : 0.f;
                v10 = (c0   <= r0+8) ? v10*RSQRT_DH*__expf(ga-a1) : 0.f;
                v11 = (c0+1 <= r0+8) ? v11*RSQRT_DH*__expf(gb-a1) : 0.f;
                rs0 += v00 + v01; rs1 += v10 + v11;
                *(__half2*)(Ch + pidx(r0,   c0, 32)) = __floats2half2_rn(v00, v01);
                *(__half2*)(Ch + pidx(r0+8, c0, 32)) = __floats2half2_rn(v10, v11);
            } else {
                v00 *= rn0; v01 *= rn0; v10 *= rn1; v11 *= rn1;
                *(float2*)(Cf + (size_t)r0*ldc + c0)     = make_float2(v00, v01);
                *(float2*)(Cf + (size_t)(r0+8)*ldc + c0) = make_float2(v10, v11);
            }
        }
        if (EPI == 1) {
            rs0 += __shfl_xor_sync(0xFFFFFFFF, rs0, 1);
            rs0 += __shfl_xor_sync(0xFFFFFFFF, rs0, 2);
            rs1 += __shfl_xor_sync(0xFFFFFFFF, rs1, 1);
            rs1 += __shfl_xor_sync(0xFFFFFFFF, rs1, 2);
            if (qc == 0) {
                atomicAdd(g_rowsum + bh*SS + r0, rs0);
                atomicAdd(g_rowsum + bh*SS + r0 + 8, rs1);
            }
        }
    }
}

// =====================================================================
// Tiled transpose to PACKED fp16: element (n=c, k=r)
// =====================================================================
__global__ void __launch_bounds__(256)
transpose_k(const float* __restrict__ in, __half* __restrict__ out,
            int R, int Ccols) {
    __shared__ float t[32][33];
    int r0 = blockIdx.y*32, c0 = blockIdx.x*32;
    int tx = threadIdx.x & 31, ty = threadIdx.x >> 5;
    int tk = R >> 6;
    #pragma unroll
    for (int i = ty; i < 32; i += 8)
        t[i][tx] = in[(size_t)(r0+i)*Ccols + c0 + tx];
    __syncthreads();
    #pragma unroll
    for (int i = ty; i < 32; i += 8)
        out[pidx(c0+i, r0+tx, tk)] = __float2half_rn(t[tx][i]);
}

// h_vt16 packed: per bh, element (row=d, k=s)
__global__ void __launch_bounds__(256)
vt_kernel() {
    __shared__ float t[32][33];
    int bh = blockIdx.z, b = bh >> 2, nh = bh & 3;
    int s0 = blockIdx.y*32, d0 = blockIdx.x*32;
    int tx = threadIdx.x & 31, ty = threadIdx.x >> 5;
    __half* dst = h_vt16 + ((size_t)bh << 20);
    #pragma unroll
    for (int i = ty; i < 32; i += 8)
        t[i][tx] = g_v[(size_t)(b*SS + s0 + i)*INNER + nh*DHH + d0 + tx];
    __syncthreads();
    #pragma unroll
    for (int i = ty; i < 32; i += 8)
        dst[pidx(d0+i, s0+tx, 32)] = __float2half_rn(t[tx][i]);
}

// x -> packed fp16 (row=tok, k 0..511)
__global__ void __launch_bounds__(256)
cvt_kernel(const float* __restrict__ in, __half* __restrict__ out) {
    int i = blockIdx.x*256 + threadIdx.x;
    out[pidx(i >> 9, i & 511, 8)] = __float2half_rn(in[i]);
}

// =====================================================================
// LayerNorm; HALF=1 writes packed __half, HALF=0 writes fp32 rows
// (float4 reduction pass)
// =====================================================================
template<int HALF>
__global__ void __launch_bounds__(256)
ln_kernel(const float* __restrict__ in, const float* __restrict__ w,
          float* __restrict__ outf, __half* __restrict__ outh, int cols) {
    int row = blockIdx.x, tid = threadIdx.x;
    const float* xr = in + (size_t)row * cols;
    const float4* xr4 = (const float4*)xr;
    int n4 = cols >> 2;
    float s = 0.f, s2 = 0.f;
    for (int c = tid; c < n4; c += 256) {
        float4 v = xr4[c];
        s  += (v.x + v.y) + (v.z + v.w);
        s2 += (v.x*v.x + v.y*v.y) + (v.z*v.z + v.w*v.w);
    }
    __shared__ float shs[256], shq[256];
    shs[tid] = s; shq[tid] = s2; __syncthreads();
    for (int off = 128; off > 0; off >>= 1) {
        if (tid < off) { shs[tid] += shs[tid+off]; shq[tid] += shq[tid+off]; }
        __syncthreads();
    }
    float mean = shs[0] / cols;
    float var = shq[0] / cols - mean * mean;
    float inv = rsqrtf(var + LN_EPS);
    int tk = cols >> 6;
    for (int c = tid; c < cols; c += 256) {
        float v = (xr[c] - mean) * inv * w[c];
        if (HALF) outh[pidx(row, c, tk)] = __float2half_rn(v);
        else      outf[(size_t)row * cols + c] = v;
    }
}

// =====================================================================
// Causal depthwise conv1d (K=4) + SiLU — rolling window, 8 s per thread
// =====================================================================
__global__ void __launch_bounds__(256)
conv_kernel(const float* __restrict__ conv_w, const float* __restrict__ conv_b) {
    int c  = blockIdx.x * 256 + threadIdx.x;
    int s0 = blockIdx.y * 8;
    int b  = blockIdx.z;
    const float* base = g_up + (size_t)(b*SS) * UPW + c;
    float* obase = g_xconv + (size_t)(b*SS) * INNER + c;
    float w0 = conv_w[c*4+0], w1 = conv_w[c*4+1];
    float w2 = conv_w[c*4+2], w3 = conv_w[c*4+3];
    float cb = conv_b[c];
    float x0 = (s0 >= 3) ? base[(size_t)(s0-3)*UPW] : 0.f;
    float x1 = (s0 >= 2) ? base[(size_t)(s0-2)*UPW] : 0.f;
    float x2 = (s0 >= 1) ? base[(size_t)(s0-1)*UPW] : 0.f;
    #pragma unroll
    for (int i = 0; i < 8; ++i) {
        int s = s0 + i;
        float x3 = base[(size_t)s*UPW];
        float acc = cb + x0*w0 + x1*w1 + x2*w2 + x3*w3;
        float sig = 1.f / (1.f + expf(-acc));
        obase[(size_t)s*INNER] = acc * sig;
        x0 = x1; x1 = x2; x2 = x3;
    }
}

// =====================================================================
// Headwise q/k/v: fp32 (gates) + packed fp16 q/k (score GEMM, per bh)
// =====================================================================
__global__ void __launch_bounds__(256)
headwise_kernel(const float* __restrict__ q_w, const float* __restrict__ q_b,
                const float* __restrict__ k_w, const float* __restrict__ k_b,
                const float* __restrict__ v_w, const float* __restrict__ v_b) {
    int idx = blockIdx.x * 256 + threadIdx.x;
    int h = idx & 511;
    int tok = idx >> 9;
    const float* xc = g_xconv + (size_t)tok * INNER + h*4;
    const float* xm = g_up    + (size_t)tok * UPW   + h*4;
    float c0=xc[0], c1=xc[1], c2=xc[2], c3=xc[3];
    float m0=xm[0], m1=xm[1], m2=xm[2], m3=xm[3];
    int wb = h * 16;
    int b = tok >> 11, s = tok & (SS-1);
    #pragma unroll
    for (int o = 0; o < 4; ++o) {
        const float* wq = q_w + wb + o*4;
        const float* wk = k_w + wb + o*4;
        const float* wv = v_w + wb + o*4;
        int oc = h*4 + o;
        float qv = q_b[oc] + wq[0]*c0 + wq[1]*c1 + wq[2]*c2 + wq[3]*c3;
        float kv = k_b[oc] + wk[0]*c0 + wk[1]*c1 + wk[2]*c2 + wk[3]*c3;
        float vv = v_b[oc] + wv[0]*m0 + wv[1]*m1 + wv[2]*m2 + wv[3]*m3;
        g_q[(size_t)tok*INNER + oc] = qv;
        g_k[(size_t)tok*INNER + oc] = kv;
        g_v[(size_t)tok*INNER + oc] = vv;
        int nh = oc >> 9, d = oc & 511;
        size_t pbase = ((size_t)(b*NHH + nh) << 20) + pidx(s, d, 8);
        h_q16[pbase] = __float2half_rn(qv);
        h_k16[pbase] = __float2half_rn(kv);
    }
}

// =====================================================================
// Gate pre-activations (fp32 path, float4 loads)
// =====================================================================
__global__ void __launch_bounds__(256)
gates_kernel(const float* __restrict__ ig_w, const float* __restrict__ ig_b,
             const float* __restrict__ fg_w, const float* __restrict__ fg_b) {
    int tok = blockIdx.x, tid = threadIdx.x;
    float aig[4] = {0,0,0,0}, afg[4] = {0,0,0,0};
    for (int f = tid*4; f < 3*INNER; f += 1024) {
        float4 xv;
        if (f < INNER)            xv = *(const float4*)(g_q + (size_t)tok*INNER + f);
        else if (f < 2*INNER)     xv = *(const float4*)(g_k + (size_t)tok*INNER + f - INNER);
        else                      xv = *(const float4*)(g_v + (size_t)tok*INNER + f - 2*INNER);
        #pragma unroll
        for (int j = 0; j < 4; ++j) {
            float xs = (j == 0) ? xv.x : (j == 1) ? xv.y : (j == 2) ? xv.z : xv.w;
            float4 wi = *(const float4*)(ig_w + (size_t)(f + j) * 4);
            float4 wf = *(const float4*)(fg_w + (size_t)(f + j) * 4);
            aig[0] += xs*wi.x; aig[1] += xs*wi.y; aig[2] += xs*wi.z; aig[3] += xs*wi.w;
            afg[0] += xs*wf.x; afg[1] += xs*wf.y; afg[2] += xs*wf.z; afg[3] += xs*wf.w;
        }
    }
    __shared__ float sh[8*256];
    #pragma unroll
    for (int n = 0; n < 4; ++n) { sh[n*256+tid] = aig[n]; sh[(4+n)*256+tid] = afg[n]; }
    __syncthreads();
    for (int off = 128; off > 0; off >>= 1) {
        if (tid < off)
            #pragma unroll
            for (int m = 0; m < 8; ++m) sh[m*256+tid] += sh[m*256+tid+off];
        __syncthreads();
    }
    if (tid == 0) {
        int b = tok >> 11, s = tok & (SS-1);
        #pragma unroll
        for (int n = 0; n < 4; ++n) {
            g_ig[(b*NHH+n)*SS + s] = sh[n*256] + ig_b[n];
            g_fg[(b*NHH+n)*SS + s] = sh[(4+n)*256] + fg_b[n];
        }
    }
}

// =====================================================================
// Per-(b,nh) scans: cum, g, a, m.  Also zeroes g_rowsum.
// =====================================================================
__global__ void __launch_bounds__(256)
scan_kernel() {
    int bh = blockIdx.x, tid = threadIdx.x;
    const int PERT = SS / 256;
    __shared__ float sh[256];
    int base = bh*SS + tid*PERT;
    float lf[PERT]; float lsum = 0.f;
    #pragma unroll
    for (int r = 0; r < PERT; ++r) {
        float f = g_fg[base + r];
        float l = (f >= 0.f) ? -log1pf(expf(-f)) : (f - log1pf(expf(f)));
        lf[r] = l; lsum += l;
    }
    sh[tid] = lsum; __syncthreads();
    for (int off = 1; off < 256; off <<= 1) {
        float v = sh[tid];
        float p = (tid >= off) ? sh[tid-off] : 0.f;
        __syncthreads();
        sh[tid] = v + p;
        __syncthreads();
    }
    float cumoff = sh[tid] - lsum;
    __syncthreads();
    float run = cumoff, lmax = -INFINITY;
    float cumv[PERT], gloc[PERT], gmax[PERT];
    #pragma unroll
    for (int r = 0; r < PERT; ++r) {
        run += lf[r];
        cumv[r] = run;
        float gg = g_ig[base + r] - run;
        gloc[r] = gg;
        lmax = fmaxf(lmax, gg);
        gmax[r] = lmax;
    }
    sh[tid] = lmax; __syncthreads();
    for (int off = 1; off < 256; off <<= 1) {
        float v = sh[tid];
        float p = (tid >= off) ? sh[tid-off] : -INFINITY;
        __syncthreads();
        sh[tid] = fmaxf(v, p);
        __syncthreads();
    }
    float exmax = (tid == 0) ? -INFINITY : sh[tid-1];
    #pragma unroll
    for (int r = 0; r < PERT; ++r) {
        float a = fmaxf(exmax, gmax[r]);
        g_gv[base + r] = gloc[r];
        g_av[base + r] = a;
        g_mv[base + r] = cumv[r] + a;
        g_rowsum[base + r] = 0.f;
    }
}

// =====================================================================
// Head group-norm + skip + output gate -> packed fp16 (down GEMM)
// (float4 reduction pass)
// =====================================================================
__global__ void __launch_bounds__(256)
hgate_kernel(const float* __restrict__ onorm_w, const float* __restrict__ skip) {
    int idx = blockIdx.x;
    int s = idx & (SS-1);
    int bhn = idx >> 11;
    int nh = bhn & 3, b = bhn >> 2;
    int tid = threadIdx.x;
    const float* hrow = g_hatt + (size_t)idx * DHH;
    const float4* h4 = (const float4*)hrow;
    float sm = 0.f, sq = 0.f;
    for (int d = tid; d < DHH/4; d += 256) {
        float4 v = h4[d];
        sm += (v.x + v.y) + (v.z + v.w);
        sq += (v.x*v.x + v.y*v.y) + (v.z*v.z + v.w*v.w);
    }
    __shared__ float shs[256], shq[256];
    shs[tid] = sm; shq[tid] = sq; __syncthreads();
    for (int off = 128; off > 0; off >>= 1) {
        if (tid < off) { shs[tid] += shs[tid+off]; shq[tid] += shq[tid+off]; }
        __syncthreads();
    }
    float mean = shs[0] / DHH;
    float var = shq[0] / DHH - mean * mean;
    float inv = rsqrtf(var + LN_EPS);
    size_t tq = (size_t)(b*SS + s);
    for (int d = tid; d < DHH; d += 256) {
        int c = nh*DHH + d;
        float hn = (hrow[d] - mean) * inv * onorm_w[c];
        float xc = g_xconv[tq*INNER + c];
        float zz = g_up[tq*UPW + INNER + c];
        float silz = zz / (1.f + expf(-zz));
        h_hg16[pidx((int)tq, c, 32)] = __float2half_rn((hn + skip[c]*xc) * silz);
    }
}

// =====================================================================
extern "C" void kernel_launch(void* const* d_in, const int* in_sizes, int n_in,
                              void* d_out, int out_size) {
    const float* x      = (const float*)d_in[0];
    const float* w_in   = (const float*)d_in[1];
    const float* b_in   = (const float*)d_in[2];
    const float* ln1_w  = (const float*)d_in[3];
    const float* w_up   = (const float*)d_in[4];
    const float* b_up   = (const float*)d_in[5];
    const float* conv_w = (const float*)d_in[6];
    const float* conv_b = (const float*)d_in[7];
    const float* q_w    = (const float*)d_in[8];
    const float* q_b    = (const float*)d_in[9];
    const float* k_w    = (const float*)d_in[10];
    const float* k_b    = (const float*)d_in[11];
    const float* v_w    = (const float*)d_in[12];
    const float* v_b    = (const float*)d_in[13];
    const float* ig_w   = (const float*)d_in[14];
    const float* ig_b   = (const float*)d_in[15];
    const float* fg_w   = (const float*)d_in[16];
    const float* fg_b   = (const float*)d_in[17];
    const float* onorm_w= (const float*)d_in[18];
    const float* skip   = (const float*)d_in[19];
    const float* w_down = (const float*)d_in[20];
    const float* b_down = (const float*)d_in[21];
    const float* post_w = (const float*)d_in[22];
    float* out = (float*)d_out;

    float *p_hin, *p_pre, *p_hatt, *p_up;
    __half *p_x16, *p_winT, *p_wupT, *p_wdnT, *p_xn16, *p_q16, *p_k16;
    __half *p_sc16, *p_vt16, *p_hg16;
    cudaGetSymbolAddress((void**)&p_hin, g_hin);
    cudaGetSymbolAddress((void**)&p_pre, g_pre);
    cudaGetSymbolAddress((void**)&p_hatt, g_hatt);
    cudaGetSymbolAddress((void**)&p_up, g_up);
    cudaGetSymbolAddress((void**)&p_x16, h_x16);
    cudaGetSymbolAddress((void**)&p_winT, h_winT16);
    cudaGetSymbolAddress((void**)&p_wupT, h_wupT16);
    cudaGetSymbolAddress((void**)&p_wdnT, h_wdnT16);
    cudaGetSymbolAddress((void**)&p_xn16, h_xn16);
    cudaGetSymbolAddress((void**)&p_q16, h_q16);
    cudaGetSymbolAddress((void**)&p_k16, h_k16);
    cudaGetSymbolAddress((void**)&p_sc16, h_sc16);
    cudaGetSymbolAddress((void**)&p_vt16, h_vt16);
    cudaGetSymbolAddress((void**)&p_hg16, h_hg16);

    static int attr_done = 0;
    if (!attr_done) {
        cudaFuncSetAttribute(mma_gemm<0>, cudaFuncAttributeMaxDynamicSharedMemorySize, SMEM_BYTES);
        cudaFuncSetAttribute(mma_gemm<1>, cudaFuncAttributeMaxDynamicSharedMemorySize, SMEM_BYTES);
        cudaFuncSetAttribute(mma_gemm<2>, cudaFuncAttributeMaxDynamicSharedMemorySize, SMEM_BYTES);
        attr_done = 1;
    }

    // weight transposes + fp16 conversion (packed layouts)
    transpose_k<<<dim3(EE/32, INF/32), 256>>>(w_in, p_winT, INF, EE);
    transpose_k<<<dim3(UPW/32, EE/32), 256>>>(w_up, p_wupT, EE, UPW);
    transpose_k<<<dim3(EE/32, INNER/32), 256>>>(w_down, p_wdnT, INNER, EE);
    cvt_kernel<<<(NTOK*INF)/256, 256>>>(x, p_x16);

    // 1. h_in = x @ w_in + b_in      (tka = 512/64 = 8)
    mma_gemm<0><<<dim3(EE/128, NTOK/128, 1), 256, SMEM_BYTES>>>(p_x16, p_winT, p_hin, nullptr, EE, 8, b_in, nullptr);
    // 2. xn = LN(h_in)  (packed fp16)
    ln_kernel<1><<<NTOK, 256>>>(p_hin, ln1_w, nullptr, p_xn16, EE);
    // 3. up = xn @ w_up + b_up       (tka = 1024/64 = 16)
    mma_gemm<0><<<dim3(UPW/128, NTOK/128, 1), 256, SMEM_BYTES>>>(p_xn16, p_wupT, p_up, nullptr, UPW, 16, b_up, nullptr);
    // 4. conv + SiLU
    conv_kernel<<<dim3(INNER/256, SS/8, BB), 256>>>(conv_w, conv_b);
    // 5. headwise q/k/v
    headwise_kernel<<<(NTOK*512)/256, 256>>>(q_w, q_b, k_w, k_b, v_w, v_b);
    // 6-7. gates + scans (scan zeroes g_rowsum)
    gates_kernel<<<NTOK, 256>>>(ig_w, ig_b, fg_w, fg_b);
    scan_kernel<<<BHN, 256>>>();
    // transpose V per head (packed)
    vt_kernel<<<dim3(DHH/32, SS/32, BHN), 256>>>();
    // 8. scores (causal, exp epilogue, packed fp16 out, fused row-sums; tka=8)
    mma_gemm<1><<<dim3(SS/128, SS/128, BHN), 256, SMEM_BYTES>>>(p_q16, p_k16, nullptr, p_sc16, SS, 8, nullptr, nullptr);
    // 9. h = (C * rnorm) @ V  (tka = 32, causal nch; rnorm inline from rowsum)
    mma_gemm<2><<<dim3(DHH/128, SS/128, BHN), 256, SMEM_BYTES>>>(p_sc16, p_vt16, p_hatt, nullptr, DHH, 32, nullptr, nullptr);
    // 10. head norm + skip + gate (packed fp16)
    hgate_kernel<<<BHN*SS, 256>>>(onorm_w, skip);
    // 11. y = h_gated @ w_down + b_down + h_in   (tka = 32)
    mma_gemm<0><<<dim3(EE/128, NTOK/128, 1), 256, SMEM_BYTES>>>(p_hg16, p_wdnT, p_pre, nullptr, EE, 32, b_down, p_hin);
    // 12. out = LN(pre)  (fp32 final output)
    ln_kernel<0><<<NTOK, 256>>>(p_pre, post_w, out, nullptr, EE);
}

// round 14
// speedup vs baseline: 1.0307x; 1.0084x over previous
#include <cuda_runtime.h>
#include <cuda_fp16.h>
#include <math.h>
#include <stdint.h>

// ---- problem dims ----
#define BB 2
#define SS 2048
#define INF 512
#define EE 1024
#define INNER 2048
#define UPW 4096          // 2*INNER
#define NHH 4
#define DHH 512
#define NTOK (BB*SS)      // 4096
#define BHN (BB*NHH)      // 8
#define EPS_CELL 1e-6f
#define LN_EPS 1e-5f
#define RSQRT_DH 0.044194173824159216f   // 1/sqrt(512)

// ---- fp32 scratch ----
__device__ float g_hin[NTOK*EE];
__device__ float g_up[NTOK*UPW];
__device__ float g_xconv[NTOK*INNER];
__device__ float g_v[NTOK*INNER];
__device__ float g_ig[BHN*SS];
__device__ float g_fg[BHN*SS];
__device__ float g_gv[BHN*SS];
__device__ float g_av[BHN*SS];
__device__ float g_mv[BHN*SS];
__device__ float g_rowsum[BHN*SS];
__device__ float g_hatt[8388608];     // (B*NH, S, DH)
__device__ float g_pre[NTOK*EE];
// ---- fp16 GEMM operands, PACKED tile layout:
//   element (row, k) of an operand with K = tk*64 lives at
//   block = (row/128)*tk + k/64   (16 KB = 8192 halfs per block)
//   within block: (row%128)*64 + 8*((k/8 % 8) ^ (row%8)) + k%8
__device__ __half h_x16[NTOK*INF];
__device__ __half h_winT16[EE*INF];
__device__ __half h_xn16[NTOK*EE];
__device__ __half h_wupT16[UPW*EE];
__device__ __half h_q16[NTOK*INNER];     // per-bh packed (DH k-dim)
__device__ __half h_k16[NTOK*INNER];
__device__ __half h_sc16[33554432];      // per-bh packed (S k-dim)
__device__ __half h_vt16[8388608];       // per-bh packed (S k-dim)
__device__ __half h_hg16[NTOK*INNER];
__device__ __half h_wdnT16[EE*INNER];

// =====================================================================
// helpers
// =====================================================================
__device__ __forceinline__ size_t pidx(int row, int k, int tk) {
    return (((size_t)((row >> 7) * tk + (k >> 6))) << 13)
         + (size_t)(((row & 127) << 6)
         + ((((k >> 3) & 7) ^ (row & 7)) << 3) + (k & 7));
}
__device__ __forceinline__ uint32_t smem_u32(const void* p) {
    uint32_t a;
    asm("{ .reg .u64 t; cvta.to.shared.u64 t, %1; cvt.u32.u64 %0, t; }"
        : "=r"(a) : "l"(p));
    return a;
}
__device__ __forceinline__ void bulk_cp(uint32_t dst, const void* src,
                                        uint32_t bytes, uint32_t mbar) {
    asm volatile(
        "cp.async.bulk.shared::cluster.global.mbarrier::complete_tx::bytes "
        "[%0], [%1], %2, [%3];"
        :: "r"(dst), "l"(src), "r"(bytes), "r"(mbar) : "memory");
}
__device__ __forceinline__ void mbar_init(uint32_t mbar, uint32_t cnt) {
    asm volatile("mbarrier.init.shared.b64 [%0], %1;" :: "r"(mbar), "r"(cnt) : "memory");
}
__device__ __forceinline__ void mbar_expect_tx(uint32_t mbar, uint32_t bytes) {
    asm volatile("mbarrier.arrive.expect_tx.shared.b64 _, [%0], %1;"
                 :: "r"(mbar), "r"(bytes) : "memory");
}
__device__ __forceinline__ void mbar_wait(uint32_t mbar, uint32_t parity) {
    asm volatile(
        "{\n\t.reg .pred P;\n\t"
        "WL_%=:\n\t"
        "mbarrier.try_wait.parity.acquire.cta.shared::cta.b64 P, [%0], %1, 0x989680;\n\t"
        "@P bra.uni WD_%=;\n\t"
        "bra.uni WL_%=;\n\t"
        "WD_%=:\n\t}"
        :: "r"(mbar), "r"(parity) : "memory");
}
__device__ __forceinline__ void ldsm_x4(uint32_t* r, uint32_t addr) {
    asm volatile("ldmatrix.sync.aligned.m8n8.x4.shared.b16 {%0,%1,%2,%3}, [%4];"
                 : "=r"(r[0]), "=r"(r[1]), "=r"(r[2]), "=r"(r[3]) : "r"(addr));
}
__device__ __forceinline__ void mma_f16(float* c, const uint32_t* a,
                                        const uint32_t* b) {
    asm volatile(
        "mma.sync.aligned.m16n8k16.row.col.f32.f16.f16.f32 "
        "{%0,%1,%2,%3}, {%4,%5,%6,%7}, {%8,%9}, {%0,%1,%2,%3};"
        : "+f"(c[0]), "+f"(c[1]), "+f"(c[2]), "+f"(c[3])
        : "r"(a[0]), "r"(a[1]), "r"(a[2]), "r"(a[3]), "r"(b[0]), "r"(b[1]));
}

#define STG_BYTES 32768u                 // A 16KB + B 16KB per stage
#define SMEM_BYTES (3*32768 + 64)        // 3 stages + mbarriers
#define BHALF 16384u

// =====================================================================
// FP16 mma.sync NT-GEMM on PACKED operands, 128x128 tile, K-chunk 64.
// R9 configuration: 256 threads, 3-stage bulk-copy ring; per chunk the
// compute path does LDSMs, __syncthreads (drains smem reads), tid-0
// refill, then the final MMA batch.
// EPI 0: fp32 out (+bias, +optional resid)
// EPI 1: scores -> packed fp16 out (causal + exp(g[j]-a[i])), fused row-sums
// EPI 2: AV fp32 out (row scale computed inline from rowsum/mv)
// =====================================================================
template<int EPI>
__global__ void __launch_bounds__(256, 2)
mma_gemm(const __half* __restrict__ A, const __half* __restrict__ B,
         float* __restrict__ Cf, __half* __restrict__ Ch,
         int ldc, int tka,
         const float* __restrict__ bias,
         const float* __restrict__ resid) {
    extern __shared__ __align__(1024) char smch[];
    const int tid = threadIdx.x;
    const int lane = tid & 31, wid = tid >> 5;
    const int warp_m = wid & 1, warp_n = wid >> 1;     // 2 x 4
    const int qr = lane >> 2, qc = lane & 3;
    const int mt = blockIdx.y, nt = blockIdx.x;
    const int i0 = mt * 128, j0 = nt * 128;
    const int bh = blockIdx.z;

    if (EPI == 1) {
        if (j0 > i0) return;
        A += (size_t)bh << 20;
        B += (size_t)bh << 20;
        Ch += (size_t)bh << 22;
    }
    if (EPI == 2) {
        A += (size_t)bh << 22;
        B += (size_t)bh << 20;
        Cf += (size_t)bh * SS * DHH;
    }
    const int nch = (EPI == 2) ? ((i0 >> 6) + 2) : tka;

    const __half* Ablk = A + (size_t)(mt * tka) * 8192;
    const __half* Bblk = B + (size_t)(nt * tka) * 8192;

    const uint32_t smb = smem_u32(smch);
    const uint32_t fb0 = smb + 3 * STG_BYTES;

    if (tid == 0) {
        mbar_init(fb0, 1); mbar_init(fb0 + 8, 1); mbar_init(fb0 + 16, 1);
    }
    __syncthreads();

    const int la = lane & 7, lg = lane >> 3;
    uint32_t adA[4], adB[2];
    #pragma unroll
    for (int ms = 0; ms < 4; ++ms) {
        int row = warp_m*64 + ms*16 + la + (lg & 1)*8;
        int c0 = lg >> 1;
        adA[ms] = smb + (uint32_t)(row*128 + 16*(c0 ^ (row & 7)));
    }
    #pragma unroll
    for (int nb = 0; nb < 2; ++nb) {
        int row = warp_n*32 + nb*16 + la + (lg >> 1)*8;
        int c0 = lg & 1;
        adB[nb] = smb + BHALF + (uint32_t)(row*128 + 16*(c0 ^ (row & 7)));
    }

    float acc[4][4][4];
    #pragma unroll
    for (int a = 0; a < 4; ++a)
        #pragma unroll
        for (int b = 0; b < 4; ++b)
            #pragma unroll
            for (int c = 0; c < 4; ++c) acc[a][b][c] = 0.f;

    auto issue = [&](int t) {
        if (t < nch && tid == 0) {
            int s = t % 3;
            uint32_t fb = fb0 + s*8;
            uint32_t dst = smb + (uint32_t)s * STG_BYTES;
            mbar_expect_tx(fb, 32768u);
            bulk_cp(dst,         Ablk + (size_t)t * 8192, 16384u, fb);
            bulk_cp(dst + BHALF, Bblk + (size_t)t * 8192, 16384u, fb);
        }
    };
    issue(0); issue(1); issue(2);

    for (int t = 0; t < nch; ++t) {
        const int s = t % 3;
        mbar_wait(fb0 + s*8, (uint32_t)((t / 3) & 1));

        const uint32_t stg = (uint32_t)s * STG_BYTES;
        #pragma unroll
        for (int ks = 0; ks < 4; ++ks) {
            const uint32_t kx = (uint32_t)(ks << 5);
            uint32_t a[4][4], b[2][4];
            #pragma unroll
            for (int ms = 0; ms < 4; ++ms)
                ldsm_x4(a[ms], (adA[ms] + stg) ^ kx);
            #pragma unroll
            for (int nb = 0; nb < 2; ++nb)
                ldsm_x4(b[nb], (adB[nb] + stg) ^ kx);
            if (ks == 3) {
                __syncthreads();
                issue(t + 3);
            }
            #pragma unroll
            for (int ms = 0; ms < 4; ++ms)
                #pragma unroll
                for (int nn = 0; nn < 4; ++nn)
                    mma_f16(acc[ms][nn], a[ms], &b[nn >> 1][(nn & 1) * 2]);
        }
    }

    // epilogue
    #pragma unroll
    for (int ms = 0; ms < 4; ++ms) {
        const int r0 = i0 + warp_m*64 + ms*16 + qr;
        float rs0 = 0.f, rs1 = 0.f;
        float rn0 = 0.f, rn1 = 0.f;
        if (EPI == 2) {
            float s0 = g_rowsum[bh*SS + r0], s1 = g_rowsum[bh*SS + r0 + 8];
            rn0 = 1.f / (fmaxf(fabsf(s0), expf(-g_mv[bh*SS + r0])) + EPS_CELL);
            rn1 = 1.f / (fmaxf(fabsf(s1), expf(-g_mv[bh*SS + r0 + 8])) + EPS_CELL);
        }
        #pragma unroll
        for (int ns = 0; ns < 4; ++ns) {
            const int c0 = j0 + warp_n*32 + ns*8 + qc*2;
            float v00 = acc[ms][ns][0], v01 = acc[ms][ns][1];
            float v10 = acc[ms][ns][2], v11 = acc[ms][ns][3];
            if (EPI == 0) {
                float b0 = bias[c0], b1 = bias[c0+1];
                v00 += b0; v01 += b1; v10 += b0; v11 += b1;
                if (resid) {
                    v00 += resid[(size_t)r0*ldc + c0];
                    v01 += resid[(size_t)r0*ldc + c0 + 1];
                    v10 += resid[(size_t)(r0+8)*ldc + c0];
                    v11 += resid[(size_t)(r0+8)*ldc + c0 + 1];
                }
                *(float2*)(Cf + (size_t)r0*ldc + c0)     = make_float2(v00, v01);
                *(float2*)(Cf + (size_t)(r0+8)*ldc + c0) = make_float2(v10, v11);
            } else if (EPI == 1) {
                float ga = g_gv[bh*SS + c0], gb = g_gv[bh*SS + c0 + 1];
                float a0 = g_av[bh*SS + r0], a1 = g_av[bh*SS + r0 + 8];
                v00 = (c0   <= r0  ) ? v00*RSQRT_DH*__expf(ga-a0) : 0.f;
                v01 = (c0+1 <= r0  ) ? v01*RSQRT_DH*__expf(gb-a0) : 0.f;
                v10 = (c0   <= r0+8) ? v10*RSQRT_DH*__expf(ga-a1) : 0.f;
                v11 = (c0+1 <= r0+8) ? v11*RSQRT_DH*__expf(gb-a1) : 0.f;
                rs0 += v00 + v01; rs1 += v10 + v11;
                *(__half2*)(Ch + pidx(r0,   c0, 32)) = __floats2half2_rn(v00, v01);
                *(__half2*)(Ch + pidx(r0+8, c0, 32)) = __floats2half2_rn(v10, v11);
            } else {
                v00 *= rn0; v01 *= rn0; v10 *= rn1; v11 *= rn1;
                *(float2*)(Cf + (size_t)r0*ldc + c0)     = make_float2(v00, v01);
                *(float2*)(Cf + (size_t)(r0+8)*ldc + c0) = make_float2(v10, v11);
            }
        }
        if (EPI == 1) {
            rs0 += __shfl_xor_sync(0xFFFFFFFF, rs0, 1);
            rs0 += __shfl_xor_sync(0xFFFFFFFF, rs0, 2);
            rs1 += __shfl_xor_sync(0xFFFFFFFF, rs1, 1);
            rs1 += __shfl_xor_sync(0xFFFFFFFF, rs1, 2);
            if (qc == 0) {
                atomicAdd(g_rowsum + bh*SS + r0, rs0);
                atomicAdd(g_rowsum + bh*SS + r0 + 8, rs1);
            }
        }
    }
}

// =====================================================================
// Tiled transpose to PACKED fp16: element (n=c, k=r)
// =====================================================================
__global__ void __launch_bounds__(256)
transpose_k(const float* __restrict__ in, __half* __restrict__ out,
            int R, int Ccols) {
    __shared__ float t[32][33];
    int r0 = blockIdx.y*32, c0 = blockIdx.x*32;
    int tx = threadIdx.x & 31, ty = threadIdx.x >> 5;
    int tk = R >> 6;
    #pragma unroll
    for (int i = ty; i < 32; i += 8)
        t[i][tx] = in[(size_t)(r0+i)*Ccols + c0 + tx];
    __syncthreads();
    #pragma unroll
    for (int i = ty; i < 32; i += 8)
        out[pidx(c0+i, r0+tx, tk)] = __float2half_rn(t[tx][i]);
}

// h_vt16 packed: per bh, element (row=d, k=s)
__global__ void __launch_bounds__(256)
vt_kernel() {
    __shared__ float t[32][33];
    int bh = blockIdx.z, b = bh >> 2, nh = bh & 3;
    int s0 = blockIdx.y*32, d0 = blockIdx.x*32;
    int tx = threadIdx.x & 31, ty = threadIdx.x >> 5;
    __half* dst = h_vt16 + ((size_t)bh << 20);
    #pragma unroll
    for (int i = ty; i < 32; i += 8)
        t[i][tx] = g_v[(size_t)(b*SS + s0 + i)*INNER + nh*DHH + d0 + tx];
    __syncthreads();
    #pragma unroll
    for (int i = ty; i < 32; i += 8)
        dst[pidx(d0+i, s0+tx, 32)] = __float2half_rn(t[tx][i]);
}

// x -> packed fp16 (row=tok, k 0..511)
__global__ void __launch_bounds__(256)
cvt_kernel(const float* __restrict__ in, __half* __restrict__ out) {
    int i = blockIdx.x*256 + threadIdx.x;
    out[pidx(i >> 9, i & 511, 8)] = __float2half_rn(in[i]);
}

// =====================================================================
// LayerNorm; HALF=1 writes packed __half, HALF=0 writes fp32 rows
// (float4 reduction pass)
// =====================================================================
template<int HALF>
__global__ void __launch_bounds__(256)
ln_kernel(const float* __restrict__ in, const float* __restrict__ w,
          float* __restrict__ outf, __half* __restrict__ outh, int cols) {
    int row = blockIdx.x, tid = threadIdx.x;
    const float* xr = in + (size_t)row * cols;
    const float4* xr4 = (const float4*)xr;
    int n4 = cols >> 2;
    float s = 0.f, s2 = 0.f;
    for (int c = tid; c < n4; c += 256) {
        float4 v = xr4[c];
        s  += (v.x + v.y) + (v.z + v.w);
        s2 += (v.x*v.x + v.y*v.y) + (v.z*v.z + v.w*v.w);
    }
    __shared__ float shs[256], shq[256];
    shs[tid] = s; shq[tid] = s2; __syncthreads();
    for (int off = 128; off > 0; off >>= 1) {
        if (tid < off) { shs[tid] += shs[tid+off]; shq[tid] += shq[tid+off]; }
        __syncthreads();
    }
    float mean = shs[0] / cols;
    float var = shq[0] / cols - mean * mean;
    float inv = rsqrtf(var + LN_EPS);
    int tk = cols >> 6;
    for (int c = tid; c < cols; c += 256) {
        float v = (xr[c] - mean) * inv * w[c];
        if (HALF) outh[pidx(row, c, tk)] = __float2half_rn(v);
        else      outf[(size_t)row * cols + c] = v;
    }
}

// =====================================================================
// Causal depthwise conv1d (K=4) + SiLU — rolling window, 8 s per thread
// =====================================================================
__global__ void __launch_bounds__(256)
conv_kernel(const float* __restrict__ conv_w, const float* __restrict__ conv_b) {
    int c  = blockIdx.x * 256 + threadIdx.x;
    int s0 = blockIdx.y * 8;
    int b  = blockIdx.z;
    const float* base = g_up + (size_t)(b*SS) * UPW + c;
    float* obase = g_xconv + (size_t)(b*SS) * INNER + c;
    float w0 = conv_w[c*4+0], w1 = conv_w[c*4+1];
    float w2 = conv_w[c*4+2], w3 = conv_w[c*4+3];
    float cb = conv_b[c];
    float x0 = (s0 >= 3) ? base[(size_t)(s0-3)*UPW] : 0.f;
    float x1 = (s0 >= 2) ? base[(size_t)(s0-2)*UPW] : 0.f;
    float x2 = (s0 >= 1) ? base[(size_t)(s0-1)*UPW] : 0.f;
    #pragma unroll
    for (int i = 0; i < 8; ++i) {
        int s = s0 + i;
        float x3 = base[(size_t)s*UPW];
        float acc = cb + x0*w0 + x1*w1 + x2*w2 + x3*w3;
        float sig = 1.f / (1.f + expf(-acc));
        obase[(size_t)s*INNER] = acc * sig;
        x0 = x1; x1 = x2; x2 = x3;
    }
}

// =====================================================================
// FUSED headwise q/k/v + gate pre-activations.
// One block per token (256 threads); thread owns heads 2t, 2t+1
// (8 consecutive channels d = 8t..8t+7 within one nh).
// Writes packed fp16 q/k (one 16B chunk each), fp32 v, and reduces
// ig/fg over the block.
// =====================================================================
__global__ void __launch_bounds__(256)
hwgates_kernel(const float* __restrict__ q_w, const float* __restrict__ q_b,
               const float* __restrict__ k_w, const float* __restrict__ k_b,
               const float* __restrict__ v_w, const float* __restrict__ v_b,
               const float* __restrict__ ig_w, const float* __restrict__ ig_b,
               const float* __restrict__ fg_w, const float* __restrict__ fg_b) {
    int tok = blockIdx.x, tid = threadIdx.x;
    int b = tok >> 11, s = tok & (SS-1);
    float aig[4] = {0,0,0,0}, afg[4] = {0,0,0,0};
    __half qh[8], kh[8];
    float vf[8];
    #pragma unroll
    for (int hh = 0; hh < 2; ++hh) {
        int h = tid*2 + hh;
        const float* xc = g_xconv + (size_t)tok * INNER + h*4;
        const float* xm = g_up    + (size_t)tok * UPW   + h*4;
        float4 xc4 = *(const float4*)xc;
        float4 xm4 = *(const float4*)xm;
        int wb = h * 16;
        #pragma unroll
        for (int o = 0; o < 4; ++o) {
            float4 wq = *(const float4*)(q_w + wb + o*4);
            float4 wk = *(const float4*)(k_w + wb + o*4);
            float4 wv = *(const float4*)(v_w + wb + o*4);
            int oc = h*4 + o;
            float qv = q_b[oc] + wq.x*xc4.x + wq.y*xc4.y + wq.z*xc4.z + wq.w*xc4.w;
            float kv = k_b[oc] + wk.x*xc4.x + wk.y*xc4.y + wk.z*xc4.z + wk.w*xc4.w;
            float vv = v_b[oc] + wv.x*xm4.x + wv.y*xm4.y + wv.z*xm4.z + wv.w*xm4.w;
            qh[hh*4+o] = __float2half_rn(qv);
            kh[hh*4+o] = __float2half_rn(kv);
            vf[hh*4+o] = vv;
            // gates: q at f=oc, k at INNER+oc, v at 2*INNER+oc
            float4 wiq = *(const float4*)(ig_w + (size_t)oc*4);
            float4 wik = *(const float4*)(ig_w + (size_t)(INNER+oc)*4);
            float4 wiv = *(const float4*)(ig_w + (size_t)(2*INNER+oc)*4);
            float4 wfq = *(const float4*)(fg_w + (size_t)oc*4);
            float4 wfk = *(const float4*)(fg_w + (size_t)(INNER+oc)*4);
            float4 wfv = *(const float4*)(fg_w + (size_t)(2*INNER+oc)*4);
            aig[0] += qv*wiq.x + kv*wik.x + vv*wiv.x;
            aig[1] += qv*wiq.y + kv*wik.y + vv*wiv.y;
            aig[2] += qv*wiq.z + kv*wik.z + vv*wiv.z;
            aig[3] += qv*wiq.w + kv*wik.w + vv*wiv.w;
            afg[0] += qv*wfq.x + kv*wfk.x + vv*wfv.x;
            afg[1] += qv*wfq.y + kv*wfk.y + vv*wfv.y;
            afg[2] += qv*wfq.z + kv*wfk.z + vv*wfv.z;
            afg[3] += qv*wfq.w + kv*wfk.w + vv*wfv.w;
        }
    }
    // packed q/k write: d = 8t..8t+7, nh = t>>6, contiguous 16B chunk
    {
        int nh = tid >> 6;
        int d0 = (tid * 8) & 511;
        size_t pb = ((size_t)(b*NHH + nh) << 20) + pidx(s, d0, 8);
        *(uint4*)(h_q16 + pb) = *(const uint4*)qh;
        *(uint4*)(h_k16 + pb) = *(const uint4*)kh;
    }
    // fp32 v write (row-major, contiguous 8 floats)
    {
        float* vp = g_v + (size_t)tok * INNER + tid*8;
        *(float4*)vp       = make_float4(vf[0], vf[1], vf[2], vf[3]);
        *(float4*)(vp + 4) = make_float4(vf[4], vf[5], vf[6], vf[7]);
    }
    // block-reduce gates
    __shared__ float sh[8*256];
    #pragma unroll
    for (int n = 0; n < 4; ++n) { sh[n*256+tid] = aig[n]; sh[(4+n)*256+tid] = afg[n]; }
    __syncthreads();
    for (int off = 128; off > 0; off >>= 1) {
        if (tid < off)
            #pragma unroll
            for (int m = 0; m < 8; ++m) sh[m*256+tid] += sh[m*256+tid+off];
        __syncthreads();
    }
    if (tid == 0) {
        #pragma unroll
        for (int n = 0; n < 4; ++n) {
            g_ig[(b*NHH+n)*SS + s] = sh[n*256] + ig_b[n];
            g_fg[(b*NHH+n)*SS + s] = sh[(4+n)*256] + fg_b[n];
        }
    }
}

// =====================================================================
// Per-(b,nh) scans: cum, g, a, m.  Also zeroes g_rowsum.
// =====================================================================
__global__ void __launch_bounds__(256)
scan_kernel() {
    int bh = blockIdx.x, tid = threadIdx.x;
    const int PERT = SS / 256;
    __shared__ float sh[256];
    int base = bh*SS + tid*PERT;
    float lf[PERT]; float lsum = 0.f;
    #pragma unroll
    for (int r = 0; r < PERT; ++r) {
        float f = g_fg[base + r];
        float l = (f >= 0.f) ? -log1pf(expf(-f)) : (f - log1pf(expf(f)));
        lf[r] = l; lsum += l;
    }
    sh[tid] = lsum; __syncthreads();
    for (int off = 1; off < 256; off <<= 1) {
        float v = sh[tid];
        float p = (tid >= off) ? sh[tid-off] : 0.f;
        __syncthreads();
        sh[tid] = v + p;
        __syncthreads();
    }
    float cumoff = sh[tid] - lsum;
    __syncthreads();
    float run = cumoff, lmax = -INFINITY;
    float cumv[PERT], gloc[PERT], gmax[PERT];
    #pragma unroll
    for (int r = 0; r < PERT; ++r) {
        run += lf[r];
        cumv[r] = run;
        float gg = g_ig[base + r] - run;
        gloc[r] = gg;
        lmax = fmaxf(lmax, gg);
        gmax[r] = lmax;
    }
    sh[tid] = lmax; __syncthreads();
    for (int off = 1; off < 256; off <<= 1) {
        float v = sh[tid];
        float p = (tid >= off) ? sh[tid-off] : -INFINITY;
        __syncthreads();
        sh[tid] = fmaxf(v, p);
        __syncthreads();
    }
    float exmax = (tid == 0) ? -INFINITY : sh[tid-1];
    #pragma unroll
    for (int r = 0; r < PERT; ++r) {
        float a = fmaxf(exmax, gmax[r]);
        g_gv[base + r] = gloc[r];
        g_av[base + r] = a;
        g_mv[base + r] = cumv[r] + a;
        g_rowsum[base + r] = 0.f;
    }
}

// =====================================================================
// Head group-norm + skip + output gate -> packed fp16 (down GEMM)
// (float4 reduction pass)
// =====================================================================
__global__ void __launch_bounds__(256)
hgate_kernel(const float* __restrict__ onorm_w, const float* __restrict__ skip) {
    int idx = blockIdx.x;
    int s = idx & (SS-1);
    int bhn = idx >> 11;
    int nh = bhn & 3, b = bhn >> 2;
    int tid = threadIdx.x;
    const float* hrow = g_hatt + (size_t)idx * DHH;
    const float4* h4 = (const float4*)hrow;
    float sm = 0.f, sq = 0.f;
    for (int d = tid; d < DHH/4; d += 256) {
        float4 v = h4[d];
        sm += (v.x + v.y) + (v.z + v.w);
        sq += (v.x*v.x + v.y*v.y) + (v.z*v.z + v.w*v.w);
    }
    __shared__ float shs[256], shq[256];
    shs[tid] = sm; shq[tid] = sq; __syncthreads();
    for (int off = 128; off > 0; off >>= 1) {
        if (tid < off) { shs[tid] += shs[tid+off]; shq[tid] += shq[tid+off]; }
        __syncthreads();
    }
    float mean = shs[0] / DHH;
    float var = shq[0] / DHH - mean * mean;
    float inv = rsqrtf(var + LN_EPS);
    size_t tq = (size_t)(b*SS + s);
    for (int d = tid; d < DHH; d += 256) {
        int c = nh*DHH + d;
        float hn = (hrow[d] - mean) * inv * onorm_w[c];
        float xc = g_xconv[tq*INNER + c];
        float zz = g_up[tq*UPW + INNER + c];
        float silz = zz / (1.f + expf(-zz));
        h_hg16[pidx((int)tq, c, 32)] = __float2half_rn((hn + skip[c]*xc) * silz);
    }
}

// =====================================================================
extern "C" void kernel_launch(void* const* d_in, const int* in_sizes, int n_in,
                              void* d_out, int out_size) {
    const float* x      = (const float*)d_in[0];
    const float* w_in   = (const float*)d_in[1];
    const float* b_in   = (const float*)d_in[2];
    const float* ln1_w  = (const float*)d_in[3];
    const float* w_up   = (const float*)d_in[4];
    const float* b_up   = (const float*)d_in[5];
    const float* conv_w = (const float*)d_in[6];
    const float* conv_b = (const float*)d_in[7];
    const float* q_w    = (const float*)d_in[8];
    const float* q_b    = (const float*)d_in[9];
    const float* k_w    = (const float*)d_in[10];
    const float* k_b    = (const float*)d_in[11];
    const float* v_w    = (const float*)d_in[12];
    const float* v_b    = (const float*)d_in[13];
    const float* ig_w   = (const float*)d_in[14];
    const float* ig_b   = (const float*)d_in[15];
    const float* fg_w   = (const float*)d_in[16];
    const float* fg_b   = (const float*)d_in[17];
    const float* onorm_w= (const float*)d_in[18];
    const float* skip   = (const float*)d_in[19];
    const float* w_down = (const float*)d_in[20];
    const float* b_down = (const float*)d_in[21];
    const float* post_w = (const float*)d_in[22];
    float* out = (float*)d_out;

    float *p_hin, *p_pre, *p_hatt, *p_up;
    __half *p_x16, *p_winT, *p_wupT, *p_wdnT, *p_xn16, *p_q16, *p_k16;
    __half *p_sc16, *p_vt16, *p_hg16;
    cudaGetSymbolAddress((void**)&p_hin, g_hin);
    cudaGetSymbolAddress((void**)&p_pre, g_pre);
    cudaGetSymbolAddress((void**)&p_hatt, g_hatt);
    cudaGetSymbolAddress((void**)&p_up, g_up);
    cudaGetSymbolAddress((void**)&p_x16, h_x16);
    cudaGetSymbolAddress((void**)&p_winT, h_winT16);
    cudaGetSymbolAddress((void**)&p_wupT, h_wupT16);
    cudaGetSymbolAddress((void**)&p_wdnT, h_wdnT16);
    cudaGetSymbolAddress((void**)&p_xn16, h_xn16);
    cudaGetSymbolAddress((void**)&p_q16, h_q16);
    cudaGetSymbolAddress((void**)&p_k16, h_k16);
    cudaGetSymbolAddress((void**)&p_sc16, h_sc16);
    cudaGetSymbolAddress((void**)&p_vt16, h_vt16);
    cudaGetSymbolAddress((void**)&p_hg16, h_hg16);

    static int attr_done = 0;
    if (!attr_done) {
        cudaFuncSetAttribute(mma_gemm<0>, cudaFuncAttributeMaxDynamicSharedMemorySize, SMEM_BYTES);
        cudaFuncSetAttribute(mma_gemm<1>, cudaFuncAttributeMaxDynamicSharedMemorySize, SMEM_BYTES);
        cudaFuncSetAttribute(mma_gemm<2>, cudaFuncAttributeMaxDynamicSharedMemorySize, SMEM_BYTES);
        attr_done = 1;
    }

    // weight transposes + fp16 conversion (packed layouts)
    transpose_k<<<dim3(EE/32, INF/32), 256>>>(w_in, p_winT, INF, EE);
    transpose_k<<<dim3(UPW/32, EE/32), 256>>>(w_up, p_wupT, EE, UPW);
    transpose_k<<<dim3(EE/32, INNER/32), 256>>>(w_down, p_wdnT, INNER, EE);
    cvt_kernel<<<(NTOK*INF)/256, 256>>>(x, p_x16);

    // 1. h_in = x @ w_in + b_in      (tka = 512/64 = 8)
    mma_gemm<0><<<dim3(EE/128, NTOK/128, 1), 256, SMEM_BYTES>>>(p_x16, p_winT, p_hin, nullptr, EE, 8, b_in, nullptr);
    // 2. xn = LN(h_in)  (packed fp16)
    ln_kernel<1><<<NTOK, 256>>>(p_hin, ln1_w, nullptr, p_xn16, EE);
    // 3. up = xn @ w_up + b_up       (tka = 1024/64 = 16)
    mma_gemm<0><<<dim3(UPW/128, NTOK/128, 1), 256, SMEM_BYTES>>>(p_xn16, p_wupT, p_up, nullptr, UPW, 16, b_up, nullptr);
    // 4. conv + SiLU
    conv_kernel<<<dim3(INNER/256, SS/8, BB), 256>>>(conv_w, conv_b);
    // 5. fused headwise q/k/v + gate pre-activations
    hwgates_kernel<<<NTOK, 256>>>(q_w, q_b, k_w, k_b, v_w, v_b,
                                  ig_w, ig_b, fg_w, fg_b);
    // 6. scans (zeroes g_rowsum)
    scan_kernel<<<BHN, 256>>>();
    // transpose V per head (packed)
    vt_kernel<<<dim3(DHH/32, SS/32, BHN), 256>>>();
    // 7. scores (causal, exp epilogue, packed fp16 out, fused row-sums; tka=8)
    mma_gemm<1><<<dim3(SS/128, SS/128, BHN), 256, SMEM_BYTES>>>(p_q16, p_k16, nullptr, p_sc16, SS, 8, nullptr, nullptr);
    // 8. h = (C * rnorm) @ V  (tka = 32, causal nch; rnorm inline from rowsum)
    mma_gemm<2><<<dim3(DHH/128, SS/128, BHN), 256, SMEM_BYTES>>>(p_sc16, p_vt16, p_hatt, nullptr, DHH, 32, nullptr, nullptr);
    // 9. head norm + skip + gate (packed fp16)
    hgate_kernel<<<BHN*SS, 256>>>(onorm_w, skip);
    // 10. y = h_gated @ w_down + b_down + h_in   (tka = 32)
    mma_gemm<0><<<dim3(EE/128, NTOK/128, 1), 256, SMEM_BYTES>>>(p_hg16, p_wdnT, p_pre, nullptr, EE, 32, b_down, p_hin);
    // 11. out = LN(pre)  (fp32 final output)
    ln_kernel<0><<<NTOK, 256>>>(p_pre, post_w, out, nullptr, EE);
}